// round 7
// baseline (speedup 1.0000x reference)
#include <cuda_runtime.h>
#include <cuda_bf16.h>
#include <cstdint>

#define B_  512
#define T_  100
#define L_  256
#define D_  128
#define S_  (B_*T_)        // 51200 (b,t) rows
#define NPT 511            // nodes per tree
#define NT_ (T_*NPT)       // 51100 total tree nodes
#define G_  512            // 4*D gates
#define FST 66             // fused kernel: transposed h row stride (even, padded)

// ---------------- device scratch (static globals: no allocation) ----------------
__device__ float g_wihT[D_*G_];          // w_ih transposed: [k][gate]
__device__ float g_whhT[D_*G_];          // w_hh transposed: [k][gate]
__device__ float g_bias[G_];             // b_ih + b_hh
__device__ float g_Gx[(size_t)NT_*G_];   // node_emb @ w_ih^T + bias (~104MB)
__device__ float g_H[(size_t)NT_*D_];    // per-node hidden state (26MB)
__device__ float g_C[(size_t)NT_*D_];    // per-node cell state (26MB)

// ---------------- f32x2 packed-FMA helpers (FFMA2, sm_100+ core PTX) ------------
typedef unsigned long long u64;
__device__ __forceinline__ u64 pk2(float x) {
    u64 r; asm("mov.b64 %0, {%1, %1};" : "=l"(r) : "f"(x)); return r;
}
__device__ __forceinline__ void fma2(u64& d, u64 a, u64 b) {
    asm("fma.rn.f32x2 %0, %1, %2, %0;" : "+l"(d) : "l"(a), "l"(b));
}
__device__ __forceinline__ float2 upk(u64 v) {
    float2 r; asm("mov.b64 {%0, %1}, %2;" : "=f"(r.x), "=f"(r.y) : "l"(v)); return r;
}

// ---------------- fast activations (fp32, MUFU-based, ~1e-6 rel err) ------------
__device__ __forceinline__ float sigf(float x) {
    return __fdividef(1.0f, 1.0f + __expf(-x));
}
__device__ __forceinline__ float tanhf_fast(float x) {
    return __fdividef(2.0f, 1.0f + __expf(-2.0f * x)) - 1.0f;
}

// ---------------- K0: transpose weights + fuse bias -----------------------------
__global__ void prep_kernel(const float* __restrict__ w_ih, const float* __restrict__ w_hh,
                            const float* __restrict__ b_ih, const float* __restrict__ b_hh) {
    int idx = blockIdx.x * 256 + threadIdx.x;
    if (idx < D_ * G_) {
        int g = idx / D_;
        int k = idx % D_;
        g_wihT[k * G_ + g] = w_ih[idx];
        g_whhT[k * G_ + g] = w_hh[idx];
    }
    if (idx < G_) g_bias[idx] = b_ih[idx] + b_hh[idx];
}

// ---------------- K1: Gx = node_emb @ w_ih^T + bias  (51100 x 512, K=128) -------
// 32 nodes x 512 gates per block; a-tile in smem, b direct from L2 (ulonglong2),
// accumulators packed as f32x2 gate-pairs.
__global__ void __launch_bounds__(256) gx_kernel(const float* __restrict__ node_emb) {
    __shared__ float xs[D_ * 32];    // [k][node]
    int tid = threadIdx.x;
    int n0  = blockIdx.x * 32;
    int ug  = tid >> 3;
    int sg  = tid & 7;
    {
        int row = tid >> 3;
        int kq  = tid & 7;
        int nrow = n0 + row;
#pragma unroll
        for (int j = 0; j < 4; j++) {
            int c4 = kq + 8 * j;
            float4 v = make_float4(0.f, 0.f, 0.f, 0.f);
            if (nrow < NT_) v = ((const float4*)node_emb)[(size_t)nrow * 32 + c4];
            xs[(4 * c4 + 0) * 32 + row] = v.x;
            xs[(4 * c4 + 1) * 32 + row] = v.y;
            xs[(4 * c4 + 2) * 32 + row] = v.z;
            xs[(4 * c4 + 3) * 32 + row] = v.w;
        }
    }
    __syncthreads();

    // acc2[ss][2ty+h] packs gates (4ug+128ty+2h, +1) for seq 4sg+ss
    u64 acc2[4][8];
#pragma unroll
    for (int ty = 0; ty < 4; ty++) {
        ulonglong2 bb = *(const ulonglong2*)&g_bias[4 * ug + 128 * ty];
#pragma unroll
        for (int ss = 0; ss < 4; ss++) { acc2[ss][2 * ty] = bb.x; acc2[ss][2 * ty + 1] = bb.y; }
    }

    const ulonglong2* w2 = (const ulonglong2*)g_wihT;
#pragma unroll 4
    for (int k = 0; k < 128; k++) {
        float4 a = *(const float4*)&xs[k * 32 + 4 * sg];
        u64 ad[4] = { pk2(a.x), pk2(a.y), pk2(a.z), pk2(a.w) };
#pragma unroll
        for (int ty = 0; ty < 4; ty++) {
            ulonglong2 b = __ldg(&w2[(k * G_ + 4 * ug + 128 * ty) >> 2]);   // 16B elems: idx/4
#pragma unroll
            for (int ss = 0; ss < 4; ss++) {
                fma2(acc2[ss][2 * ty],     ad[ss], b.x);
                fma2(acc2[ss][2 * ty + 1], ad[ss], b.y);
            }
        }
    }

#pragma unroll
    for (int ss = 0; ss < 4; ss++) {
        int n = n0 + 4 * sg + ss;
        if (n < NT_) {
#pragma unroll
            for (int ty = 0; ty < 4; ty++) {
                ulonglong2 v; v.x = acc2[ss][2 * ty]; v.y = acc2[ss][2 * ty + 1];
                *(ulonglong2*)&g_Gx[(size_t)n * G_ + 4 * ug + 128 * ty] = v;
            }
        }
    }
}

// ---------------- K2: fused levels 0..6 (one block per tree) --------------------
// h stored transposed [k][node] (stride FST) so f32x2 packs TWO PARENTS per FMA
// with a single broadcast ld.shared.b64. gs holds recurrent pre-acts [pi][512].
template<int NP, bool LAST>
__device__ __forceinline__ void run_level(const float4* __restrict__ w4,
                                          const float* hp, const float* cp,
                                          float* hc, float* cc, float* gs,
                                          size_t tb, int tid) {
    constexpr int NC = 2 * NP;
    const int ga = tid, gb = tid + 256;

    if constexpr (NP == 1) {
        float accA = 0.f, accB = 0.f;
#pragma unroll 4
        for (int k4 = 0; k4 < 32; k4++) {
            float4 wa = __ldg(&w4[ga * 32 + k4]);
            float4 wb = __ldg(&w4[gb * 32 + k4]);
            float h0 = hp[(4 * k4 + 0) * FST];
            float h1 = hp[(4 * k4 + 1) * FST];
            float h2 = hp[(4 * k4 + 2) * FST];
            float h3 = hp[(4 * k4 + 3) * FST];
            accA = fmaf(wa.x, h0, fmaf(wa.y, h1, fmaf(wa.z, h2, fmaf(wa.w, h3, accA))));
            accB = fmaf(wb.x, h0, fmaf(wb.y, h1, fmaf(wb.z, h2, fmaf(wb.w, h3, accB))));
        }
        gs[ga] = accA;
        gs[gb] = accB;
    } else {
        u64 accA[NP / 2], accB[NP / 2];
#pragma unroll
        for (int pj = 0; pj < NP / 2; pj++) { accA[pj] = 0ULL; accB[pj] = 0ULL; }
#pragma unroll 2
        for (int k4 = 0; k4 < 32; k4++) {
            float4 wa = __ldg(&w4[ga * 32 + k4]);
            float4 wb = __ldg(&w4[gb * 32 + k4]);
            u64 wad[4] = { pk2(wa.x), pk2(wa.y), pk2(wa.z), pk2(wa.w) };
            u64 wbd[4] = { pk2(wb.x), pk2(wb.y), pk2(wb.z), pk2(wb.w) };
#pragma unroll
            for (int pj = 0; pj < NP / 2; pj++) {
#pragma unroll
                for (int kk = 0; kk < 4; kk++) {
                    u64 hpair = *(const u64*)&hp[(4 * k4 + kk) * FST + 2 * pj];
                    fma2(accA[pj], wad[kk], hpair);
                    fma2(accB[pj], wbd[kk], hpair);
                }
            }
        }
#pragma unroll
        for (int pj = 0; pj < NP / 2; pj++) {
            float2 a2 = upk(accA[pj]);
            float2 b2 = upk(accB[pj]);
            gs[(2 * pj) * G_ + ga] = a2.x;  gs[(2 * pj + 1) * G_ + ga] = a2.y;
            gs[(2 * pj) * G_ + gb] = b2.x;  gs[(2 * pj + 1) * G_ + gb] = b2.y;
        }
    }
    __syncthreads();

    // Phase B: activations for NC children x 128 units
#pragma unroll 2
    for (int cell = tid; cell < NC * 128; cell += 256) {
        int ci = cell >> 7, u = cell & 127, pi = ci >> 1;
        size_t gid = tb + (NC - 1) + ci;
        const float* gx = g_Gx + gid * (size_t)G_;
        const float* gr = gs + pi * G_;
        float pri = gr[u]       + gx[u];
        float prf = gr[128 + u] + gx[128 + u];
        float prg = gr[256 + u] + gx[256 + u];
        float pro = gr[384 + u] + gx[384 + u];
        float cpv = cp[pi * 128 + u];
        float c = fmaf(sigf(prf), cpv, sigf(pri) * tanhf_fast(prg));
        float h = sigf(pro) * tanhf_fast(c);
        cc[ci * 128 + u] = c;
        hc[u * FST + ci] = h;
        if (LAST) { g_H[gid * 128 + u] = h; g_C[gid * 128 + u] = c; }
    }
    __syncthreads();
}

__global__ void __launch_bounds__(256) fused_kernel(const float* __restrict__ w_hh) {
    extern __shared__ float sm[];
    float* hA = sm;                  // [128][FST] transposed h, 8448 floats
    float* hB = sm + 8448;
    float* cA = sm + 16896;          // [64][128]
    float* cB = cA + 8192;
    float* gs = cB + 8192;           // [32][512]
    int t = blockIdx.x, tid = threadIdx.x;
    size_t tb = (size_t)t * NPT;

    // level 0: root (h=c=0 -> pure activation of Gx)
    if (tid < 128) {
        const float* gx = g_Gx + tb * (size_t)G_;
        float iv = sigf(gx[tid]);
        float gv = tanhf_fast(gx[256 + tid]);
        float ov = sigf(gx[384 + tid]);
        float c  = iv * gv;
        cA[tid] = c;
        hA[tid * FST] = ov * tanhf_fast(c);
    }
    __syncthreads();

    const float4* w4 = (const float4*)w_hh;
    run_level<1,  false>(w4, hA, cA, hB, cB, gs, tb, tid);
    run_level<2,  false>(w4, hB, cB, hA, cA, gs, tb, tid);
    run_level<4,  false>(w4, hA, cA, hB, cB, gs, tb, tid);
    run_level<8,  false>(w4, hB, cB, hA, cA, gs, tb, tid);
    run_level<16, false>(w4, hA, cA, hB, cB, gs, tb, tid);
    run_level<32, true >(w4, hB, cB, hA, cA, gs, tb, tid);
}

// ---------------- K3: big tree levels (d=7,8) -----------------------------------
// 32 parents x 512 gates per block, f32x2 gate-pair accumulators, b via L2.
__global__ void __launch_bounds__(256) level_kernel(int shift, int pcnt) {
    __shared__ float hs[D_ * 32];    // [k][parent]
    int tid  = threadIdx.x;
    int p0   = blockIdx.x * 32;
    int half = 1 << shift;
    int ug   = tid >> 3;
    int sg   = tid & 7;

    {
        int row = tid >> 3;
        int kq  = tid & 7;
        int pi  = p0 + row;
        const float4* src = nullptr;
        if (pi < pcnt) {
            int t = pi >> shift;
            int j = pi & (half - 1);
            size_t pgid = (size_t)t * NPT + (half - 1) + j;
            src = (const float4*)(g_H + pgid * D_);
        }
#pragma unroll
        for (int jj = 0; jj < 4; jj++) {
            int c4 = kq + 8 * jj;
            float4 v = src ? src[c4] : make_float4(0.f, 0.f, 0.f, 0.f);
            hs[(4 * c4 + 0) * 32 + row] = v.x;
            hs[(4 * c4 + 1) * 32 + row] = v.y;
            hs[(4 * c4 + 2) * 32 + row] = v.z;
            hs[(4 * c4 + 3) * 32 + row] = v.w;
        }
    }
    __syncthreads();

    u64 acc2[4][8];
#pragma unroll
    for (int ss = 0; ss < 4; ss++)
#pragma unroll
        for (int j = 0; j < 8; j++) acc2[ss][j] = 0ULL;

    const ulonglong2* w2 = (const ulonglong2*)g_whhT;
#pragma unroll 4
    for (int k = 0; k < 128; k++) {
        float4 a = *(const float4*)&hs[k * 32 + 4 * sg];
        u64 ad[4] = { pk2(a.x), pk2(a.y), pk2(a.z), pk2(a.w) };
#pragma unroll
        for (int ty = 0; ty < 4; ty++) {
            ulonglong2 b = __ldg(&w2[(k * G_ + 4 * ug + 128 * ty) >> 2]);   // 16B elems: idx/4
#pragma unroll
            for (int ss = 0; ss < 4; ss++) {
                fma2(acc2[ss][2 * ty],     ad[ss], b.x);
                fma2(acc2[ss][2 * ty + 1], ad[ss], b.y);
            }
        }
    }

    float acc[4][16];
#pragma unroll
    for (int ss = 0; ss < 4; ss++)
#pragma unroll
        for (int ty = 0; ty < 4; ty++) {
            float2 v0 = upk(acc2[ss][2 * ty]);
            float2 v1 = upk(acc2[ss][2 * ty + 1]);
            acc[ss][ty * 4 + 0] = v0.x; acc[ss][ty * 4 + 1] = v0.y;
            acc[ss][ty * 4 + 2] = v1.x; acc[ss][ty * 4 + 3] = v1.y;
        }

    // epilogue: apply both children of each parent
#pragma unroll
    for (int ss = 0; ss < 4; ss++) {
        int pi = p0 + 4 * sg + ss;
        if (pi >= pcnt) continue;
        int t = pi >> shift;
        int j = pi & (half - 1);
        int plocal = (half - 1) + j;
        size_t tb = (size_t)t * NPT;
        float4 cp4 = *(const float4*)(g_C + (tb + plocal) * D_ + 4 * ug);
        float cp[4] = {cp4.x, cp4.y, cp4.z, cp4.w};
#pragma unroll
        for (int ch = 0; ch < 2; ch++) {
            size_t cgid = tb + 2 * plocal + 1 + ch;
            const float* gxr = g_Gx + cgid * (size_t)G_;
            float4 gi = *(const float4*)(gxr + 4 * ug);
            float4 gf = *(const float4*)(gxr + 128 + 4 * ug);
            float4 gg = *(const float4*)(gxr + 256 + 4 * ug);
            float4 go = *(const float4*)(gxr + 384 + 4 * ug);
            float giv[4] = {gi.x, gi.y, gi.z, gi.w};
            float gfv[4] = {gf.x, gf.y, gf.z, gf.w};
            float ggv[4] = {gg.x, gg.y, gg.z, gg.w};
            float gov[4] = {go.x, go.y, go.z, go.w};
            float hv[4], cv[4];
#pragma unroll
            for (int uu = 0; uu < 4; uu++) {
                float iv = sigf(acc[ss][0 + uu] + giv[uu]);
                float fv = sigf(acc[ss][4 + uu] + gfv[uu]);
                float gv = tanhf_fast(acc[ss][8 + uu] + ggv[uu]);
                float ov = sigf(acc[ss][12 + uu] + gov[uu]);
                float c  = fmaf(fv, cp[uu], iv * gv);
                cv[uu] = c;
                hv[uu] = ov * tanhf_fast(c);
            }
            *(float4*)(g_C + cgid * D_ + 4 * ug) = make_float4(cv[0], cv[1], cv[2], cv[3]);
            *(float4*)(g_H + cgid * D_ + 4 * ug) = make_float4(hv[0], hv[1], hv[2], hv[3]);
        }
    }
}

// ---------------- K4: argmax leaf + gather output -------------------------------
__global__ void gather_kernel(const float* __restrict__ cross, float* __restrict__ out) {
    int s = blockIdx.x * 8 + threadIdx.y;
    int lane = threadIdx.x;
    const float4* r4 = (const float4*)(cross + (size_t)s * L_);
    float best = -1e30f;
    int   bidx = 0x7fffffff;
#pragma unroll
    for (int j = 0; j < 2; j++) {
        float4 v = r4[lane * 2 + j];
        int base = lane * 8 + 4 * j;
        if (v.x > best) { best = v.x; bidx = base + 0; }
        if (v.y > best) { best = v.y; bidx = base + 1; }
        if (v.z > best) { best = v.z; bidx = base + 2; }
        if (v.w > best) { best = v.w; bidx = base + 3; }
    }
#pragma unroll
    for (int off = 16; off; off >>= 1) {
        float ob = __shfl_xor_sync(0xffffffffu, best, off);
        int   oi = __shfl_xor_sync(0xffffffffu, bidx, off);
        if (ob > best || (ob == best && oi < bidx)) { best = ob; bidx = oi; }
    }
    bool act = best > 0.0f;
    int t = s % T_;
    size_t gid = (size_t)t * NPT + (L_ - 1) + bidx;
    float4 v = act ? ((const float4*)(g_H + gid * D_))[lane]
                   : make_float4(0.f, 0.f, 0.f, 0.f);
    ((float4*)(out + (size_t)s * D_))[lane] = v;
}

// ---------------- launch ---------------------------------------------------------
#define FUSED_SMEM ((8448*2 + 8192*2 + 16384) * 4)   // 198656 B

extern "C" void kernel_launch(void* const* d_in, const int* in_sizes, int n_in,
                              void* d_out, int out_size) {
    const float* cross    = (const float*)d_in[0];
    const float* node_emb = (const float*)d_in[1];
    const float* w_ih     = (const float*)d_in[2];
    const float* w_hh     = (const float*)d_in[3];
    const float* b_ih     = (const float*)d_in[4];
    const float* b_hh     = (const float*)d_in[5];
    float* out = (float*)d_out;

    cudaFuncSetAttribute(fused_kernel,
                         cudaFuncAttributeMaxDynamicSharedMemorySize, FUSED_SMEM);

    prep_kernel<<<256, 256>>>(w_ih, w_hh, b_ih, b_hh);
    gx_kernel<<<(NT_ + 31) / 32, 256>>>(node_emb);
    fused_kernel<<<T_, 256, FUSED_SMEM>>>(w_hh);
    level_kernel<<<(T_ * 64 + 31) / 32, 256>>>(6, T_ * 64);    // depth-6 parents
    level_kernel<<<(T_ * 128 + 31) / 32, 256>>>(7, T_ * 128);  // depth-7 parents
    gather_kernel<<<S_ / 8, dim3(32, 8)>>>(cross, out);
}

// round 8
// speedup vs baseline: 1.2240x; 1.2240x over previous
#include <cuda_runtime.h>
#include <cuda_bf16.h>
#include <cstdint>

#define B_  512
#define T_  100
#define L_  256
#define D_  128
#define S_  (B_*T_)        // 51200 (b,t) rows
#define NPT 511            // nodes per tree
#define NT_ (T_*NPT)       // 51100 total tree nodes
#define G_  512            // 4*D gates
#define FST 66             // fused kernel: transposed h row stride (even, padded)

// ---------------- device scratch (static globals: no allocation) ----------------
__device__ float g_wihT[D_*G_];          // w_ih transposed: [k][gate]
__device__ float g_whhT[D_*G_];          // w_hh transposed: [k][gate]
__device__ float g_bias[G_];             // b_ih + b_hh
__device__ float g_Gx[(size_t)NT_*G_];   // node_emb @ w_ih^T + bias (~104MB)
__device__ float g_H[(size_t)NT_*D_];    // per-node hidden state (26MB)
__device__ float g_C[(size_t)NT_*D_];    // per-node cell state (26MB)

// ---------------- f32x2 packed-FMA helpers (FFMA2, sm_100+ core PTX) ------------
typedef unsigned long long u64;
__device__ __forceinline__ u64 pk2(float x) {
    u64 r; asm("mov.b64 %0, {%1, %1};" : "=l"(r) : "f"(x)); return r;
}
__device__ __forceinline__ void fma2(u64& d, u64 a, u64 b) {
    asm("fma.rn.f32x2 %0, %1, %2, %0;" : "+l"(d) : "l"(a), "l"(b));
}
__device__ __forceinline__ float2 upk(u64 v) {
    float2 r; asm("mov.b64 {%0, %1}, %2;" : "=f"(r.x), "=f"(r.y) : "l"(v)); return r;
}

// ---------------- fast activations (fp32, MUFU-based, ~1e-6 rel err) ------------
__device__ __forceinline__ float sigf(float x) {
    return __fdividef(1.0f, 1.0f + __expf(-x));
}
__device__ __forceinline__ float tanhf_fast(float x) {
    return __fdividef(2.0f, 1.0f + __expf(-2.0f * x)) - 1.0f;
}

// ---------------- K0: transpose weights + fuse bias -----------------------------
__global__ void prep_kernel(const float* __restrict__ w_ih, const float* __restrict__ w_hh,
                            const float* __restrict__ b_ih, const float* __restrict__ b_hh) {
    int idx = blockIdx.x * 256 + threadIdx.x;
    if (idx < D_ * G_) {
        int g = idx / D_;
        int k = idx % D_;
        g_wihT[k * G_ + g] = w_ih[idx];
        g_whhT[k * G_ + g] = w_hh[idx];
    }
    if (idx < G_) g_bias[idx] = b_ih[idx] + b_hh[idx];
}

// ================ shared GEMM core: 32 rows x 512 gates, K=128 ==================
// a-tile [k][row] in smem (xs), weights staged per 16-k chunk into ws (smem),
// f32x2 gate-pair accumulators; b-pairs read directly as ulonglong2 from ws.
__device__ __forceinline__ void gemm32x512(const float* __restrict__ xs,
                                           float* __restrict__ ws,
                                           const float* __restrict__ wT,
                                           u64 acc2[4][8], int tid, int ug, int sg) {
    for (int kc = 0; kc < 8; kc++) {
#pragma unroll
        for (int j = 0; j < 8; j++)
            ((float4*)ws)[j * 256 + tid] = ((const float4*)wT)[kc * 2048 + j * 256 + tid];
        __syncthreads();
#pragma unroll
        for (int k = 0; k < 16; k++) {
            float4 a = *(const float4*)&xs[(kc * 16 + k) * 32 + 4 * sg];
            u64 ad[4] = { pk2(a.x), pk2(a.y), pk2(a.z), pk2(a.w) };
#pragma unroll
            for (int ty = 0; ty < 4; ty++) {
                ulonglong2 b = *(const ulonglong2*)&ws[k * G_ + 4 * ug + 128 * ty];
#pragma unroll
                for (int ss = 0; ss < 4; ss++) {
                    fma2(acc2[ss][2 * ty],     ad[ss], b.x);
                    fma2(acc2[ss][2 * ty + 1], ad[ss], b.y);
                }
            }
        }
        __syncthreads();
    }
}

// ---------------- K1: Gx = node_emb @ w_ih^T + bias  (51100 x 512, K=128) -------
__global__ void __launch_bounds__(256) gx_kernel(const float* __restrict__ node_emb) {
    __shared__ float xs[D_ * 32];    // [k][node]
    __shared__ float ws[16 * G_];    // [k][gate] staged chunk
    int tid = threadIdx.x;
    int n0  = blockIdx.x * 32;
    int ug  = tid >> 3;
    int sg  = tid & 7;
    {
        int row = tid >> 3;
        int kq  = tid & 7;
        int nrow = n0 + row;
#pragma unroll
        for (int j = 0; j < 4; j++) {
            int c4 = kq + 8 * j;
            float4 v = make_float4(0.f, 0.f, 0.f, 0.f);
            if (nrow < NT_) v = ((const float4*)node_emb)[(size_t)nrow * 32 + c4];
            xs[(4 * c4 + 0) * 32 + row] = v.x;
            xs[(4 * c4 + 1) * 32 + row] = v.y;
            xs[(4 * c4 + 2) * 32 + row] = v.z;
            xs[(4 * c4 + 3) * 32 + row] = v.w;
        }
    }

    // acc2[ss][2ty+h] packs gates (4ug+128ty+2h, +1) for row 4sg+ss, init = bias
    u64 acc2[4][8];
#pragma unroll
    for (int ty = 0; ty < 4; ty++) {
        ulonglong2 bb = *(const ulonglong2*)&g_bias[4 * ug + 128 * ty];
#pragma unroll
        for (int ss = 0; ss < 4; ss++) { acc2[ss][2 * ty] = bb.x; acc2[ss][2 * ty + 1] = bb.y; }
    }
    __syncthreads();

    gemm32x512(xs, ws, g_wihT, acc2, tid, ug, sg);

#pragma unroll
    for (int ss = 0; ss < 4; ss++) {
        int n = n0 + 4 * sg + ss;
        if (n < NT_) {
#pragma unroll
            for (int ty = 0; ty < 4; ty++) {
                ulonglong2 v; v.x = acc2[ss][2 * ty]; v.y = acc2[ss][2 * ty + 1];
                *(ulonglong2*)&g_Gx[(size_t)n * G_ + 4 * ug + 128 * ty] = v;
            }
        }
    }
}

// ---------------- K2: fused levels 0..6 (one block per tree) --------------------
template<int NP, bool LAST>
__device__ __forceinline__ void run_level(const float4* __restrict__ w4,
                                          const float* hp, const float* cp,
                                          float* hc, float* cc, float* gs,
                                          size_t tb, int tid) {
    constexpr int NC = 2 * NP;
    const int ga = tid, gb = tid + 256;

    if constexpr (NP == 1) {
        float accA = 0.f, accB = 0.f;
#pragma unroll 4
        for (int k4 = 0; k4 < 32; k4++) {
            float4 wa = __ldg(&w4[ga * 32 + k4]);
            float4 wb = __ldg(&w4[gb * 32 + k4]);
            float h0 = hp[(4 * k4 + 0) * FST];
            float h1 = hp[(4 * k4 + 1) * FST];
            float h2 = hp[(4 * k4 + 2) * FST];
            float h3 = hp[(4 * k4 + 3) * FST];
            accA = fmaf(wa.x, h0, fmaf(wa.y, h1, fmaf(wa.z, h2, fmaf(wa.w, h3, accA))));
            accB = fmaf(wb.x, h0, fmaf(wb.y, h1, fmaf(wb.z, h2, fmaf(wb.w, h3, accB))));
        }
        gs[ga] = accA;
        gs[gb] = accB;
    } else {
        u64 accA[NP / 2], accB[NP / 2];
#pragma unroll
        for (int pj = 0; pj < NP / 2; pj++) { accA[pj] = 0ULL; accB[pj] = 0ULL; }
#pragma unroll 2
        for (int k4 = 0; k4 < 32; k4++) {
            float4 wa = __ldg(&w4[ga * 32 + k4]);
            float4 wb = __ldg(&w4[gb * 32 + k4]);
            u64 wad[4] = { pk2(wa.x), pk2(wa.y), pk2(wa.z), pk2(wa.w) };
            u64 wbd[4] = { pk2(wb.x), pk2(wb.y), pk2(wb.z), pk2(wb.w) };
#pragma unroll
            for (int pj = 0; pj < NP / 2; pj++) {
#pragma unroll
                for (int kk = 0; kk < 4; kk++) {
                    u64 hpair = *(const u64*)&hp[(4 * k4 + kk) * FST + 2 * pj];
                    fma2(accA[pj], wad[kk], hpair);
                    fma2(accB[pj], wbd[kk], hpair);
                }
            }
        }
#pragma unroll
        for (int pj = 0; pj < NP / 2; pj++) {
            float2 a2 = upk(accA[pj]);
            float2 b2 = upk(accB[pj]);
            gs[(2 * pj) * G_ + ga] = a2.x;  gs[(2 * pj + 1) * G_ + ga] = a2.y;
            gs[(2 * pj) * G_ + gb] = b2.x;  gs[(2 * pj + 1) * G_ + gb] = b2.y;
        }
    }
    __syncthreads();

#pragma unroll 2
    for (int cell = tid; cell < NC * 128; cell += 256) {
        int ci = cell >> 7, u = cell & 127, pi = ci >> 1;
        size_t gid = tb + (NC - 1) + ci;
        const float* gx = g_Gx + gid * (size_t)G_;
        const float* gr = gs + pi * G_;
        float pri = gr[u]       + gx[u];
        float prf = gr[128 + u] + gx[128 + u];
        float prg = gr[256 + u] + gx[256 + u];
        float pro = gr[384 + u] + gx[384 + u];
        float cpv = cp[pi * 128 + u];
        float c = fmaf(sigf(prf), cpv, sigf(pri) * tanhf_fast(prg));
        float h = sigf(pro) * tanhf_fast(c);
        cc[ci * 128 + u] = c;
        hc[u * FST + ci] = h;
        if (LAST) { g_H[gid * 128 + u] = h; g_C[gid * 128 + u] = c; }
    }
    __syncthreads();
}

__global__ void __launch_bounds__(256) fused_kernel(const float* __restrict__ w_hh) {
    extern __shared__ float sm[];
    float* hA = sm;                  // [128][FST] transposed h
    float* hB = sm + 8448;
    float* cA = sm + 16896;          // [64][128]
    float* cB = cA + 8192;
    float* gs = cB + 8192;           // [32][512]
    int t = blockIdx.x, tid = threadIdx.x;
    size_t tb = (size_t)t * NPT;

    if (tid < 128) {
        const float* gx = g_Gx + tb * (size_t)G_;
        float iv = sigf(gx[tid]);
        float gv = tanhf_fast(gx[256 + tid]);
        float ov = sigf(gx[384 + tid]);
        float c  = iv * gv;
        cA[tid] = c;
        hA[tid * FST] = ov * tanhf_fast(c);
    }
    __syncthreads();

    const float4* w4 = (const float4*)w_hh;
    run_level<1,  false>(w4, hA, cA, hB, cB, gs, tb, tid);
    run_level<2,  false>(w4, hB, cB, hA, cA, gs, tb, tid);
    run_level<4,  false>(w4, hA, cA, hB, cB, gs, tb, tid);
    run_level<8,  false>(w4, hB, cB, hA, cA, gs, tb, tid);
    run_level<16, false>(w4, hA, cA, hB, cB, gs, tb, tid);
    run_level<32, true >(w4, hB, cB, hA, cA, gs, tb, tid);
}

// ---------------- K3: big tree levels (d=6,7 parents) ---------------------------
__global__ void __launch_bounds__(256) level_kernel(int shift, int pcnt) {
    __shared__ float hs[D_ * 32];    // [k][parent]
    __shared__ float ws[16 * G_];    // [k][gate] staged chunk of w_hh^T
    int tid  = threadIdx.x;
    int p0   = blockIdx.x * 32;
    int half = 1 << shift;
    int ug   = tid >> 3;
    int sg   = tid & 7;

    {
        int row = tid >> 3;
        int kq  = tid & 7;
        int pi  = p0 + row;
        const float4* src = nullptr;
        if (pi < pcnt) {
            int t = pi >> shift;
            int j = pi & (half - 1);
            size_t pgid = (size_t)t * NPT + (half - 1) + j;
            src = (const float4*)(g_H + pgid * D_);
        }
#pragma unroll
        for (int jj = 0; jj < 4; jj++) {
            int c4 = kq + 8 * jj;
            float4 v = src ? src[c4] : make_float4(0.f, 0.f, 0.f, 0.f);
            hs[(4 * c4 + 0) * 32 + row] = v.x;
            hs[(4 * c4 + 1) * 32 + row] = v.y;
            hs[(4 * c4 + 2) * 32 + row] = v.z;
            hs[(4 * c4 + 3) * 32 + row] = v.w;
        }
    }

    u64 acc2[4][8];
#pragma unroll
    for (int ss = 0; ss < 4; ss++)
#pragma unroll
        for (int j = 0; j < 8; j++) acc2[ss][j] = 0ULL;
    __syncthreads();

    gemm32x512(hs, ws, g_whhT, acc2, tid, ug, sg);

    float acc[4][16];
#pragma unroll
    for (int ss = 0; ss < 4; ss++)
#pragma unroll
        for (int ty = 0; ty < 4; ty++) {
            float2 v0 = upk(acc2[ss][2 * ty]);
            float2 v1 = upk(acc2[ss][2 * ty + 1]);
            acc[ss][ty * 4 + 0] = v0.x; acc[ss][ty * 4 + 1] = v0.y;
            acc[ss][ty * 4 + 2] = v1.x; acc[ss][ty * 4 + 3] = v1.y;
        }

#pragma unroll
    for (int ss = 0; ss < 4; ss++) {
        int pi = p0 + 4 * sg + ss;
        if (pi >= pcnt) continue;
        int t = pi >> shift;
        int j = pi & (half - 1);
        int plocal = (half - 1) + j;
        size_t tb = (size_t)t * NPT;
        float4 cp4 = *(const float4*)(g_C + (tb + plocal) * D_ + 4 * ug);
        float cp[4] = {cp4.x, cp4.y, cp4.z, cp4.w};
#pragma unroll
        for (int ch = 0; ch < 2; ch++) {
            size_t cgid = tb + 2 * plocal + 1 + ch;
            const float* gxr = g_Gx + cgid * (size_t)G_;
            float4 gi = *(const float4*)(gxr + 4 * ug);
            float4 gf = *(const float4*)(gxr + 128 + 4 * ug);
            float4 gg = *(const float4*)(gxr + 256 + 4 * ug);
            float4 go = *(const float4*)(gxr + 384 + 4 * ug);
            float giv[4] = {gi.x, gi.y, gi.z, gi.w};
            float gfv[4] = {gf.x, gf.y, gf.z, gf.w};
            float ggv[4] = {gg.x, gg.y, gg.z, gg.w};
            float gov[4] = {go.x, go.y, go.z, go.w};
            float hv[4], cv[4];
#pragma unroll
            for (int uu = 0; uu < 4; uu++) {
                float iv = sigf(acc[ss][0 + uu] + giv[uu]);
                float fv = sigf(acc[ss][4 + uu] + gfv[uu]);
                float gv = tanhf_fast(acc[ss][8 + uu] + ggv[uu]);
                float ov = sigf(acc[ss][12 + uu] + gov[uu]);
                float c  = fmaf(fv, cp[uu], iv * gv);
                cv[uu] = c;
                hv[uu] = ov * tanhf_fast(c);
            }
            *(float4*)(g_C + cgid * D_ + 4 * ug) = make_float4(cv[0], cv[1], cv[2], cv[3]);
            *(float4*)(g_H + cgid * D_ + 4 * ug) = make_float4(hv[0], hv[1], hv[2], hv[3]);
        }
    }
}

// ---------------- K4: argmax leaf + gather output -------------------------------
__global__ void gather_kernel(const float* __restrict__ cross, float* __restrict__ out) {
    int s = blockIdx.x * 8 + threadIdx.y;
    int lane = threadIdx.x;
    const float4* r4 = (const float4*)(cross + (size_t)s * L_);
    float best = -1e30f;
    int   bidx = 0x7fffffff;
#pragma unroll
    for (int j = 0; j < 2; j++) {
        float4 v = r4[lane * 2 + j];
        int base = lane * 8 + 4 * j;
        if (v.x > best) { best = v.x; bidx = base + 0; }
        if (v.y > best) { best = v.y; bidx = base + 1; }
        if (v.z > best) { best = v.z; bidx = base + 2; }
        if (v.w > best) { best = v.w; bidx = base + 3; }
    }
#pragma unroll
    for (int off = 16; off; off >>= 1) {
        float ob = __shfl_xor_sync(0xffffffffu, best, off);
        int   oi = __shfl_xor_sync(0xffffffffu, bidx, off);
        if (ob > best || (ob == best && oi < bidx)) { best = ob; bidx = oi; }
    }
    bool act = best > 0.0f;
    int t = s % T_;
    size_t gid = (size_t)t * NPT + (L_ - 1) + bidx;
    float4 v = act ? ((const float4*)(g_H + gid * D_))[lane]
                   : make_float4(0.f, 0.f, 0.f, 0.f);
    ((float4*)(out + (size_t)s * D_))[lane] = v;
}

// ---------------- launch ---------------------------------------------------------
#define FUSED_SMEM ((8448*2 + 8192*2 + 16384) * 4)   // 198656 B

extern "C" void kernel_launch(void* const* d_in, const int* in_sizes, int n_in,
                              void* d_out, int out_size) {
    const float* cross    = (const float*)d_in[0];
    const float* node_emb = (const float*)d_in[1];
    const float* w_ih     = (const float*)d_in[2];
    const float* w_hh     = (const float*)d_in[3];
    const float* b_ih     = (const float*)d_in[4];
    const float* b_hh     = (const float*)d_in[5];
    float* out = (float*)d_out;

    cudaFuncSetAttribute(fused_kernel,
                         cudaFuncAttributeMaxDynamicSharedMemorySize, FUSED_SMEM);

    prep_kernel<<<256, 256>>>(w_ih, w_hh, b_ih, b_hh);
    gx_kernel<<<(NT_ + 31) / 32, 256>>>(node_emb);
    fused_kernel<<<T_, 256, FUSED_SMEM>>>(w_hh);
    level_kernel<<<(T_ * 64 + 31) / 32, 256>>>(6, T_ * 64);    // depth-6 parents
    level_kernel<<<(T_ * 128 + 31) / 32, 256>>>(7, T_ * 128);  // depth-7 parents
    gather_kernel<<<S_ / 8, dim3(32, 8)>>>(cross, out);
}

// round 9
// speedup vs baseline: 1.2914x; 1.0551x over previous
#include <cuda_runtime.h>
#include <cuda_bf16.h>
#include <cstdint>

#define B_  512
#define T_  100
#define L_  256
#define D_  128
#define S_  (B_*T_)        // 51200 (b,t) rows
#define NPT 511            // nodes per tree
#define NT_ (T_*NPT)       // 51100 total tree nodes
#define G_  512            // 4*D gates
#define FST 66             // fused kernel: transposed h row stride (even, padded)

// ---------------- device scratch (static globals: no allocation) ----------------
__device__ float g_wihT[D_*G_];          // w_ih transposed: [k][gate]
__device__ float g_whhT[D_*G_];          // w_hh transposed: [k][gate]
__device__ float g_bias[G_];             // b_ih + b_hh
__device__ float g_Gx[(size_t)NT_*G_];   // node_emb @ w_ih^T + bias (~104MB)
__device__ float g_H[(size_t)NT_*D_];    // per-node hidden state (26MB)
__device__ float g_C[(size_t)NT_*D_];    // per-node cell state (26MB)

// ---------------- f32x2 packed-FMA helpers (FFMA2, sm_100+ core PTX) ------------
typedef unsigned long long u64;
__device__ __forceinline__ u64 pk2(float x) {
    u64 r; asm("mov.b64 %0, {%1, %1};" : "=l"(r) : "f"(x)); return r;
}
__device__ __forceinline__ void fma2(u64& d, u64 a, u64 b) {
    asm("fma.rn.f32x2 %0, %1, %2, %0;" : "+l"(d) : "l"(a), "l"(b));
}
__device__ __forceinline__ float2 upk(u64 v) {
    float2 r; asm("mov.b64 {%0, %1}, %2;" : "=f"(r.x), "=f"(r.y) : "l"(v)); return r;
}

// ---------------- cp.async helpers (sm_80+ core ISA) ----------------------------
__device__ __forceinline__ uint32_t smem_u32(const void* p) {
    uint32_t a;
    asm("{ .reg .u64 t; cvta.to.shared.u64 t, %1; cvt.u32.u64 %0, t; }" : "=r"(a) : "l"(p));
    return a;
}
__device__ __forceinline__ void cp16(uint32_t saddr, const void* gaddr) {
    asm volatile("cp.async.ca.shared.global [%0], [%1], 16;" :: "r"(saddr), "l"(gaddr) : "memory");
}
#define CP_COMMIT() asm volatile("cp.async.commit_group;" ::: "memory")
#define CP_WAIT(n)  asm volatile("cp.async.wait_group %0;" :: "n"(n) : "memory")

// ---------------- fast activations (fp32, MUFU-based, ~1e-6 rel err) ------------
__device__ __forceinline__ float sigf(float x) {
    return __fdividef(1.0f, 1.0f + __expf(-x));
}
__device__ __forceinline__ float tanhf_fast(float x) {
    return __fdividef(2.0f, 1.0f + __expf(-2.0f * x)) - 1.0f;
}

// ---------------- K0: transpose weights + fuse bias -----------------------------
__global__ void prep_kernel(const float* __restrict__ w_ih, const float* __restrict__ w_hh,
                            const float* __restrict__ b_ih, const float* __restrict__ b_hh) {
    int idx = blockIdx.x * 256 + threadIdx.x;
    if (idx < D_ * G_) {
        int g = idx / D_;
        int k = idx % D_;
        g_wihT[k * G_ + g] = w_ih[idx];
        g_whhT[k * G_ + g] = w_hh[idx];
    }
    if (idx < G_) g_bias[idx] = b_ih[idx] + b_hh[idx];
}

// ================ shared GEMM core: RB rows x 512 gates, K=128 ==================
// a-tile [k][RB] in smem, weights cp.async double-buffered 16-k chunks,
// f32x2 gate-pair accumulators; b-pairs read as ulonglong2 from smem.
template<int SS>   // rows per thread; RB = 8*SS
__device__ __forceinline__ void gemm_core(const float* __restrict__ xs,
                                          float* __restrict__ ws, uint32_t ws_s,
                                          const float* __restrict__ wT,
                                          u64 (&acc2)[SS][8], int tid, int ug, int sg) {
    constexpr int RB = 8 * SS;
    {   // stage chunk 0
        const float4* src = (const float4*)wT;
#pragma unroll
        for (int j = 0; j < 8; j++)
            cp16(ws_s + (uint32_t)(j * 256 + tid) * 16u, src + j * 256 + tid);
        CP_COMMIT();
    }
    for (int kc = 0; kc < 8; kc++) {
        const float* cur = ws + (kc & 1) * 8192;
        if (kc < 7) {   // stage next chunk into the other buffer
            const float4* src = (const float4*)(wT + (kc + 1) * 8192);
            uint32_t dst = ws_s + (uint32_t)((kc + 1) & 1) * 32768u;
#pragma unroll
            for (int j = 0; j < 8; j++)
                cp16(dst + (uint32_t)(j * 256 + tid) * 16u, src + j * 256 + tid);
            CP_COMMIT();
            CP_WAIT(1);
        } else {
            CP_WAIT(0);
        }
        __syncthreads();
#pragma unroll
        for (int k = 0; k < 16; k++) {
            u64 ad[SS];
            if constexpr (SS == 4) {
                float4 a = *(const float4*)&xs[(kc * 16 + k) * RB + 4 * sg];
                ad[0] = pk2(a.x); ad[1] = pk2(a.y); ad[2] = pk2(a.z); ad[3] = pk2(a.w);
            } else {
                float2 a = *(const float2*)&xs[(kc * 16 + k) * RB + 2 * sg];
                ad[0] = pk2(a.x); ad[1] = pk2(a.y);
            }
#pragma unroll
            for (int ty = 0; ty < 4; ty++) {
                ulonglong2 b = *(const ulonglong2*)&cur[k * G_ + 4 * ug + 128 * ty];
#pragma unroll
                for (int ss = 0; ss < SS; ss++) {
                    fma2(acc2[ss][2 * ty],     ad[ss], b.x);
                    fma2(acc2[ss][2 * ty + 1], ad[ss], b.y);
                }
            }
        }
        __syncthreads();   // all warps done with 'cur' before it is re-staged
    }
}

// ---------------- K1: Gx = node_emb @ w_ih^T + bias  (51100 x 512, K=128) -------
#define GX_SMEM ((4096 + 16384) * 4)   // xs 16KB + ws 64KB
__global__ void __launch_bounds__(256, 2) gx_kernel(const float* __restrict__ node_emb) {
    extern __shared__ float dsm[];
    float* xs = dsm;            // [k][32]
    float* ws = dsm + 4096;     // 2 x 16x512 chunks
    int tid = threadIdx.x;
    int n0  = blockIdx.x * 32;
    int ug  = tid >> 3;
    int sg  = tid & 7;
    {
        int row = tid >> 3;
        int kq  = tid & 7;
        int nrow = n0 + row;
#pragma unroll
        for (int j = 0; j < 4; j++) {
            int c4 = kq + 8 * j;
            float4 v = make_float4(0.f, 0.f, 0.f, 0.f);
            if (nrow < NT_) v = ((const float4*)node_emb)[(size_t)nrow * 32 + c4];
            xs[(4 * c4 + 0) * 32 + row] = v.x;
            xs[(4 * c4 + 1) * 32 + row] = v.y;
            xs[(4 * c4 + 2) * 32 + row] = v.z;
            xs[(4 * c4 + 3) * 32 + row] = v.w;
        }
    }

    u64 acc2[4][8];
#pragma unroll
    for (int ty = 0; ty < 4; ty++) {
        ulonglong2 bb = *(const ulonglong2*)&g_bias[4 * ug + 128 * ty];
#pragma unroll
        for (int ss = 0; ss < 4; ss++) { acc2[ss][2 * ty] = bb.x; acc2[ss][2 * ty + 1] = bb.y; }
    }
    __syncthreads();

    gemm_core<4>(xs, ws, smem_u32(ws), g_wihT, acc2, tid, ug, sg);

#pragma unroll
    for (int ss = 0; ss < 4; ss++) {
        int n = n0 + 4 * sg + ss;
        if (n < NT_) {
#pragma unroll
            for (int ty = 0; ty < 4; ty++) {
                ulonglong2 v; v.x = acc2[ss][2 * ty]; v.y = acc2[ss][2 * ty + 1];
                *(ulonglong2*)&g_Gx[(size_t)n * G_ + 4 * ug + 128 * ty] = v;
            }
        }
    }
}

// ---------------- K2: fused levels 0..6 (one block per tree) --------------------
template<int NP, bool LAST>
__device__ __forceinline__ void run_level(const float4* __restrict__ w4,
                                          const float* hp, const float* cp,
                                          float* hc, float* cc, float* gs,
                                          size_t tb, int tid) {
    constexpr int NC = 2 * NP;
    const int ga = tid, gb = tid + 256;

    if constexpr (NP == 1) {
        float accA = 0.f, accB = 0.f;
#pragma unroll 4
        for (int k4 = 0; k4 < 32; k4++) {
            float4 wa = __ldg(&w4[ga * 32 + k4]);
            float4 wb = __ldg(&w4[gb * 32 + k4]);
            float h0 = hp[(4 * k4 + 0) * FST];
            float h1 = hp[(4 * k4 + 1) * FST];
            float h2 = hp[(4 * k4 + 2) * FST];
            float h3 = hp[(4 * k4 + 3) * FST];
            accA = fmaf(wa.x, h0, fmaf(wa.y, h1, fmaf(wa.z, h2, fmaf(wa.w, h3, accA))));
            accB = fmaf(wb.x, h0, fmaf(wb.y, h1, fmaf(wb.z, h2, fmaf(wb.w, h3, accB))));
        }
        gs[ga] = accA;
        gs[gb] = accB;
    } else {
        u64 accA[NP / 2], accB[NP / 2];
#pragma unroll
        for (int pj = 0; pj < NP / 2; pj++) { accA[pj] = 0ULL; accB[pj] = 0ULL; }
#pragma unroll 2
        for (int k4 = 0; k4 < 32; k4++) {
            float4 wa = __ldg(&w4[ga * 32 + k4]);
            float4 wb = __ldg(&w4[gb * 32 + k4]);
            u64 wad[4] = { pk2(wa.x), pk2(wa.y), pk2(wa.z), pk2(wa.w) };
            u64 wbd[4] = { pk2(wb.x), pk2(wb.y), pk2(wb.z), pk2(wb.w) };
#pragma unroll
            for (int pj = 0; pj < NP / 2; pj++) {
#pragma unroll
                for (int kk = 0; kk < 4; kk++) {
                    u64 hpair = *(const u64*)&hp[(4 * k4 + kk) * FST + 2 * pj];
                    fma2(accA[pj], wad[kk], hpair);
                    fma2(accB[pj], wbd[kk], hpair);
                }
            }
        }
#pragma unroll
        for (int pj = 0; pj < NP / 2; pj++) {
            float2 a2 = upk(accA[pj]);
            float2 b2 = upk(accB[pj]);
            gs[(2 * pj) * G_ + ga] = a2.x;  gs[(2 * pj + 1) * G_ + ga] = a2.y;
            gs[(2 * pj) * G_ + gb] = b2.x;  gs[(2 * pj + 1) * G_ + gb] = b2.y;
        }
    }
    __syncthreads();

#pragma unroll 2
    for (int cell = tid; cell < NC * 128; cell += 256) {
        int ci = cell >> 7, u = cell & 127, pi = ci >> 1;
        size_t gid = tb + (NC - 1) + ci;
        const float* gx = g_Gx + gid * (size_t)G_;
        const float* gr = gs + pi * G_;
        float pri = gr[u]       + gx[u];
        float prf = gr[128 + u] + gx[128 + u];
        float prg = gr[256 + u] + gx[256 + u];
        float pro = gr[384 + u] + gx[384 + u];
        float cpv = cp[pi * 128 + u];
        float c = fmaf(sigf(prf), cpv, sigf(pri) * tanhf_fast(prg));
        float h = sigf(pro) * tanhf_fast(c);
        cc[ci * 128 + u] = c;
        hc[u * FST + ci] = h;
        if (LAST) { g_H[gid * 128 + u] = h; g_C[gid * 128 + u] = c; }
    }
    __syncthreads();
}

__global__ void __launch_bounds__(256) fused_kernel(const float* __restrict__ w_hh) {
    extern __shared__ float sm[];
    float* hA = sm;                  // [128][FST] transposed h
    float* hB = sm + 8448;
    float* cA = sm + 16896;          // [64][128]
    float* cB = cA + 8192;
    float* gs = cB + 8192;           // [32][512]
    int t = blockIdx.x, tid = threadIdx.x;
    size_t tb = (size_t)t * NPT;

    if (tid < 128) {
        const float* gx = g_Gx + tb * (size_t)G_;
        float iv = sigf(gx[tid]);
        float gv = tanhf_fast(gx[256 + tid]);
        float ov = sigf(gx[384 + tid]);
        float c  = iv * gv;
        cA[tid] = c;
        hA[tid * FST] = ov * tanhf_fast(c);
    }
    __syncthreads();

    const float4* w4 = (const float4*)w_hh;
    run_level<1,  false>(w4, hA, cA, hB, cB, gs, tb, tid);
    run_level<2,  false>(w4, hB, cB, hA, cA, gs, tb, tid);
    run_level<4,  false>(w4, hA, cA, hB, cB, gs, tb, tid);
    run_level<8,  false>(w4, hB, cB, hA, cA, gs, tb, tid);
    run_level<16, false>(w4, hA, cA, hB, cB, gs, tb, tid);
    run_level<32, true >(w4, hB, cB, hA, cA, gs, tb, tid);
}

// ---------------- K3: big tree levels (d=6,7 parents) ---------------------------
// RB = 8*SS parents x 512 gates per block; cp.async double-buffered weights.
template<int SS>
__global__ void __launch_bounds__(256, 2) level_kernel(int shift, int pcnt) {
    constexpr int RB = 8 * SS;
    extern __shared__ float dsm[];
    float* xs = dsm;                 // [k][RB]
    float* ws = dsm + RB * 128;      // 2 x 16x512 chunks
    int tid  = threadIdx.x;
    int p0   = blockIdx.x * RB;
    int half = 1 << shift;
    int ug   = tid >> 3;
    int sg   = tid & 7;

    {   // load RB parent h rows transposed into xs
        constexpr int TPR = 256 / RB;            // threads per row
        int row = tid / TPR;
        int kq  = tid % TPR;
        int pi  = p0 + row;
        const float4* src = nullptr;
        if (pi < pcnt) {
            int t = pi >> shift;
            int j = pi & (half - 1);
            size_t pgid = (size_t)t * NPT + (half - 1) + j;
            src = (const float4*)(g_H + pgid * D_);
        }
#pragma unroll
        for (int jj = 0; jj < 32 / TPR; jj++) {
            int c4 = kq + TPR * jj;
            float4 v = src ? src[c4] : make_float4(0.f, 0.f, 0.f, 0.f);
            xs[(4 * c4 + 0) * RB + row] = v.x;
            xs[(4 * c4 + 1) * RB + row] = v.y;
            xs[(4 * c4 + 2) * RB + row] = v.z;
            xs[(4 * c4 + 3) * RB + row] = v.w;
        }
    }

    u64 acc2[SS][8];
#pragma unroll
    for (int ss = 0; ss < SS; ss++)
#pragma unroll
        for (int j = 0; j < 8; j++) acc2[ss][j] = 0ULL;
    __syncthreads();

    gemm_core<SS>(xs, ws, smem_u32(ws), g_whhT, acc2, tid, ug, sg);

#pragma unroll
    for (int ss = 0; ss < SS; ss++) {
        int pi = p0 + SS * sg + ss;
        if (pi >= pcnt) continue;
        float2 v0 = upk(acc2[ss][0]), v1 = upk(acc2[ss][1]);
        float2 v2 = upk(acc2[ss][2]), v3 = upk(acc2[ss][3]);
        float2 v4 = upk(acc2[ss][4]), v5 = upk(acc2[ss][5]);
        float2 v6 = upk(acc2[ss][6]), v7 = upk(acc2[ss][7]);
        float acc[16] = { v0.x, v0.y, v1.x, v1.y,   // gate type i, units 4ug..
                          v2.x, v2.y, v3.x, v3.y,   // f
                          v4.x, v4.y, v5.x, v5.y,   // g
                          v6.x, v6.y, v7.x, v7.y }; // o
        int t = pi >> shift;
        int j = pi & (half - 1);
        int plocal = (half - 1) + j;
        size_t tb = (size_t)t * NPT;
        float4 cp4 = *(const float4*)(g_C + (tb + plocal) * D_ + 4 * ug);
        float cp[4] = {cp4.x, cp4.y, cp4.z, cp4.w};
#pragma unroll
        for (int ch = 0; ch < 2; ch++) {
            size_t cgid = tb + 2 * plocal + 1 + ch;
            const float* gxr = g_Gx + cgid * (size_t)G_;
            float4 gi = *(const float4*)(gxr + 4 * ug);
            float4 gf = *(const float4*)(gxr + 128 + 4 * ug);
            float4 gg = *(const float4*)(gxr + 256 + 4 * ug);
            float4 go = *(const float4*)(gxr + 384 + 4 * ug);
            float giv[4] = {gi.x, gi.y, gi.z, gi.w};
            float gfv[4] = {gf.x, gf.y, gf.z, gf.w};
            float ggv[4] = {gg.x, gg.y, gg.z, gg.w};
            float gov[4] = {go.x, go.y, go.z, go.w};
            float hv[4], cv[4];
#pragma unroll
            for (int uu = 0; uu < 4; uu++) {
                float iv = sigf(acc[0 + uu]  + giv[uu]);
                float fv = sigf(acc[4 + uu]  + gfv[uu]);
                float gv = tanhf_fast(acc[8 + uu] + ggv[uu]);
                float ov = sigf(acc[12 + uu] + gov[uu]);
                float c  = fmaf(fv, cp[uu], iv * gv);
                cv[uu] = c;
                hv[uu] = ov * tanhf_fast(c);
            }
            *(float4*)(g_C + cgid * D_ + 4 * ug) = make_float4(cv[0], cv[1], cv[2], cv[3]);
            *(float4*)(g_H + cgid * D_ + 4 * ug) = make_float4(hv[0], hv[1], hv[2], hv[3]);
        }
    }
}

// ---------------- K4: argmax leaf + gather output -------------------------------
__global__ void gather_kernel(const float* __restrict__ cross, float* __restrict__ out) {
    int s = blockIdx.x * 8 + threadIdx.y;
    int lane = threadIdx.x;
    const float4* r4 = (const float4*)(cross + (size_t)s * L_);
    float best = -1e30f;
    int   bidx = 0x7fffffff;
#pragma unroll
    for (int j = 0; j < 2; j++) {
        float4 v = r4[lane * 2 + j];
        int base = lane * 8 + 4 * j;
        if (v.x > best) { best = v.x; bidx = base + 0; }
        if (v.y > best) { best = v.y; bidx = base + 1; }
        if (v.z > best) { best = v.z; bidx = base + 2; }
        if (v.w > best) { best = v.w; bidx = base + 3; }
    }
#pragma unroll
    for (int off = 16; off; off >>= 1) {
        float ob = __shfl_xor_sync(0xffffffffu, best, off);
        int   oi = __shfl_xor_sync(0xffffffffu, bidx, off);
        if (ob > best || (ob == best && oi < bidx)) { best = ob; bidx = oi; }
    }
    bool act = best > 0.0f;
    int t = s % T_;
    size_t gid = (size_t)t * NPT + (L_ - 1) + bidx;
    float4 v = act ? ((const float4*)(g_H + gid * D_))[lane]
                   : make_float4(0.f, 0.f, 0.f, 0.f);
    ((float4*)(out + (size_t)s * D_))[lane] = v;
}

// ---------------- launch ---------------------------------------------------------
#define FUSED_SMEM ((8448*2 + 8192*2 + 16384) * 4)   // 198656 B
#define LV16_SMEM  ((16*128 + 16384) * 4)            // 73728 B
#define LV32_SMEM  ((32*128 + 16384) * 4)            // 81920 B

extern "C" void kernel_launch(void* const* d_in, const int* in_sizes, int n_in,
                              void* d_out, int out_size) {
    const float* cross    = (const float*)d_in[0];
    const float* node_emb = (const float*)d_in[1];
    const float* w_ih     = (const float*)d_in[2];
    const float* w_hh     = (const float*)d_in[3];
    const float* b_ih     = (const float*)d_in[4];
    const float* b_hh     = (const float*)d_in[5];
    float* out = (float*)d_out;

    cudaFuncSetAttribute(fused_kernel,
                         cudaFuncAttributeMaxDynamicSharedMemorySize, FUSED_SMEM);
    cudaFuncSetAttribute(gx_kernel,
                         cudaFuncAttributeMaxDynamicSharedMemorySize, GX_SMEM);
    cudaFuncSetAttribute(level_kernel<2>,
                         cudaFuncAttributeMaxDynamicSharedMemorySize, LV16_SMEM);
    cudaFuncSetAttribute(level_kernel<4>,
                         cudaFuncAttributeMaxDynamicSharedMemorySize, LV32_SMEM);

    prep_kernel<<<256, 256>>>(w_ih, w_hh, b_ih, b_hh);
    gx_kernel<<<(NT_ + 31) / 32, 256, GX_SMEM>>>(node_emb);
    fused_kernel<<<T_, 256, FUSED_SMEM>>>(w_hh);
    level_kernel<2><<<(T_ * 64 + 15) / 16, 256, LV16_SMEM>>>(6, T_ * 64);    // d6: 400 blocks
    level_kernel<4><<<(T_ * 128 + 31) / 32, 256, LV32_SMEM>>>(7, T_ * 128);  // d7: 400 blocks
    gather_kernel<<<S_ / 8, dim3(32, 8)>>>(cross, out);
}